// round 10
// baseline (speedup 1.0000x reference)
#include <cuda_runtime.h>
#include <cstdint>

#define S_  128
#define E_  256
#define HD_ 512

// Unified W stream: 256 superchunks u=h*32+it(k8 slice), each [slot<4][n<64][kp<8] = 8KB.
// slot: 0=K 1=V 2=Q 3=R. Pairing: kp=2t -> k=it*8+t ; kp=2t+1 -> k=it*8+t+4.
__device__ __align__(16) float g_W[256 * 2048];
// Per-CTA Q scratch: 128 rows x 64 cols (pairing/physical col order), 32KB each.
__device__ __align__(16) float g_Q[1024 * 128 * 64];

// smem floats: Xp[128][264] @0 | Wc 2x2048 @33792 | Ks[128][72] @37888 | Vt[64][136] @47104
#define SMEM_BYTES 223232

__device__ __forceinline__ float f2tf(float x) {
    uint32_t u; asm("cvt.rna.tf32.f32 %0, %1;" : "=r"(u) : "f"(x)); return __uint_as_float(u);
}
__device__ __forceinline__ uint32_t fau(float x) { return __float_as_uint(x); }

__device__ __forceinline__ void mma8(float c[4],
                                     uint32_t a0, uint32_t a1, uint32_t a2, uint32_t a3,
                                     uint32_t b0, uint32_t b1) {
    asm volatile(
        "mma.sync.aligned.m16n8k8.row.col.f32.tf32.tf32.f32 "
        "{%0,%1,%2,%3},{%4,%5,%6,%7},{%8,%9},{%0,%1,%2,%3};"
        : "+f"(c[0]), "+f"(c[1]), "+f"(c[2]), "+f"(c[3])
        : "r"(a0), "r"(a1), "r"(a2), "r"(a3), "r"(b0), "r"(b1));
}
__device__ __forceinline__ void cpa16(void* smem_dst, const void* gsrc) {
    uint32_t s = (uint32_t)__cvta_generic_to_shared(smem_dst);
    asm volatile("cp.async.cg.shared.global [%0], [%1], 16;" :: "r"(s), "l"(gsrc));
}

// ---------------------------------------------------------------------------
// Prep: round W to tf32, pack unified k8 superchunks.
// ---------------------------------------------------------------------------
__global__ void prep_kernel(const float* __restrict__ wq, const float* __restrict__ wk,
                            const float* __restrict__ wv, const float* __restrict__ wr) {
    const float* Ws[4] = {wk, wv, wq, wr};   // slot order K,V,Q,R
    int idx = blockIdx.x * blockDim.x + threadIdx.x;
    if (idx >= 256 * 2048) return;
    int kp   = idx & 7;
    int n    = (idx >> 3) & 63;
    int slot = (idx >> 9) & 3;
    int it   = (idx >> 11) & 31;
    int h    = idx >> 16;
    int k = it * 8 + (kp >> 1) + (kp & 1) * 4;
    g_W[idx] = f2tf(Ws[slot][(size_t)k * HD_ + h * 64 + n]);
}

// ---------------------------------------------------------------------------
// Fused MHA: one CTA per batch, 8 warps.
// ---------------------------------------------------------------------------
__global__ void __launch_bounds__(256, 1)
mha_kernel(const float* __restrict__ X, float* __restrict__ Out) {
    extern __shared__ float sm[];
    int b = blockIdx.x, tid = threadIdx.x;
    int w = tid >> 5, lane = tid & 31, g = lane >> 2, t = lane & 3;
    int slot = w >> 1, r64 = (w & 1) * 64;

    float* Wc = sm + 33792;
    float* Ks = sm + 37888;
    float* Vt = sm + 47104;
    float* gQb = g_Q + (size_t)b * 8192;

    // prologue: prefetch superchunk 0 (8KB)
    {
        const char* src = (const char*)g_W;
        cpa16((char*)Wc + tid * 16, src + tid * 16);
        cpa16((char*)Wc + tid * 16 + 4096, src + tid * 16 + 4096);
        asm volatile("cp.async.commit_group;" ::: "memory");
    }

    // Stage X -> Xp (tf32 round + k-pairing, stride 264).
    const float* Xg = X + (size_t)b * S_ * E_;
    for (int i = tid; i < S_ * E_ / 4; i += 256) {
        int r = i >> 6, c4 = (i & 63) * 4;
        float4 v = *(const float4*)&Xg[r * E_ + c4];
        float vv[4] = {v.x, v.y, v.z, v.w};
#pragma unroll
        for (int e = 0; e < 4; ++e) {
            int col = c4 + e, kt = col >> 3, q = col & 7;
            int kp = kt * 8 + ((q < 4) ? 2 * q : 2 * (q - 4) + 1);
            sm[r * 264 + kp] = f2tf(vv[e]);
        }
    }

    const float L2E = 1.4426950408889634f;

    for (int h = 0; h < 8; ++h) {
        size_t ob = (size_t)b * S_ * HD_ + (size_t)h * 64;

        // ========== unified projection phase: K,V,Q,R in 2-warp teams, Mt=4 ==========
        float acc[4][8][4];
#pragma unroll
        for (int m = 0; m < 4; ++m)
#pragma unroll
            for (int j = 0; j < 8; ++j)
#pragma unroll
                for (int i = 0; i < 4; ++i) acc[m][j][i] = 0.0f;

        for (int it = 0; it < 32; ++it) {
            int u = h * 32 + it;
            asm volatile("cp.async.wait_group 0;" ::: "memory");   // superchunk u landed
            __syncthreads();                                       // visible; buf (u+1)&1 free
            if (u + 1 < 256) {
                const char* src = (const char*)g_W + (size_t)(u + 1) * 8192;
                char* dst = (char*)Wc + ((u + 1) & 1) * 8192;
                cpa16(dst + tid * 16, src + tid * 16);
                cpa16(dst + tid * 16 + 4096, src + tid * 16 + 4096);
                asm volatile("cp.async.commit_group;" ::: "memory");
            }
            const float* Wb = Wc + (u & 1) * 2048 + slot * 512;
            float2 Bf[8];
#pragma unroll
            for (int j = 0; j < 8; ++j)
                Bf[j] = *(const float2*)&Wb[(j * 8 + g) * 8 + 2 * t];
#pragma unroll
            for (int m = 0; m < 4; ++m) {
                int rr = r64 + m * 16;
                float2 alo = *(const float2*)&sm[(rr + g) * 264 + it * 8 + 2 * t];
                float2 ahi = *(const float2*)&sm[(rr + g + 8) * 264 + it * 8 + 2 * t];
                uint32_t a0 = fau(alo.x), a1 = fau(ahi.x), a2 = fau(alo.y), a3 = fau(ahi.y);
#pragma unroll
                for (int j = 0; j < 8; ++j)
                    mma8(acc[m][j], a0, a1, a2, a3, fau(Bf[j].x), fau(Bf[j].y));
            }
        }

        // ---- scatter results: K->Ks, V->Vt, Q->gmem scratch (tf32), R->Out (raw) ----
        if (slot == 0) {
#pragma unroll
            for (int m = 0; m < 4; ++m) {
                int rr = r64 + m * 16;
#pragma unroll
                for (int j = 0; j < 8; ++j) {
                    *(float2*)&Ks[(rr + g) * 72 + j * 8 + 2 * t] =
                        make_float2(f2tf(acc[m][j][0]), f2tf(acc[m][j][1]));
                    *(float2*)&Ks[(rr + g + 8) * 72 + j * 8 + 2 * t] =
                        make_float2(f2tf(acc[m][j][2]), f2tf(acc[m][j][3]));
                }
            }
        } else if (slot == 1) {
#pragma unroll
            for (int m = 0; m < 4; ++m) {
                int rr = r64 + m * 16;
#pragma unroll
                for (int j = 0; j < 8; ++j) {
                    Vt[(j * 8 + 2 * t) * 136 + rr + g]         = f2tf(acc[m][j][0]);
                    Vt[(j * 8 + 2 * t + 1) * 136 + rr + g]     = f2tf(acc[m][j][1]);
                    Vt[(j * 8 + 2 * t) * 136 + rr + g + 8]     = f2tf(acc[m][j][2]);
                    Vt[(j * 8 + 2 * t + 1) * 136 + rr + g + 8] = f2tf(acc[m][j][3]);
                }
            }
        } else if (slot == 2) {
#pragma unroll
            for (int m = 0; m < 4; ++m) {
                int rr = r64 + m * 16;
#pragma unroll
                for (int j = 0; j < 8; ++j) {
                    *(float2*)&gQb[(rr + g) * 64 + j * 8 + 2 * t] =
                        make_float2(f2tf(acc[m][j][0]), f2tf(acc[m][j][1]));
                    *(float2*)&gQb[(rr + g + 8) * 64 + j * 8 + 2 * t] =
                        make_float2(f2tf(acc[m][j][2]), f2tf(acc[m][j][3]));
                }
            }
        } else {
#pragma unroll
            for (int m = 0; m < 4; ++m) {
                int rr = r64 + m * 16;
#pragma unroll
                for (int j = 0; j < 8; ++j) {
                    *(float2*)&Out[ob + (size_t)(rr + g) * HD_ + j * 8 + 2 * t] =
                        make_float2(acc[m][j][0], acc[m][j][1]);
                    *(float2*)&Out[ob + (size_t)(rr + g + 8) * HD_ + j * 8 + 2 * t] =
                        make_float2(acc[m][j][2], acc[m][j][3]);
                }
            }
        }
        __syncthreads();   // Ks/Vt/gQ/Out(R) all visible CTA-wide

        // ========== attention: each warp owns 16 rows ==========
        int r0 = w * 16;

        // Q A-frags from scratch (pairing order preserved)
        float2 qlo[8], qhi[8];
#pragma unroll
        for (int jq = 0; jq < 8; ++jq) {
            qlo[jq] = *(const float2*)&gQb[(r0 + g) * 64 + jq * 8 + 2 * t];
            qhi[jq] = *(const float2*)&gQb[(r0 + g + 8) * 64 + jq * 8 + 2 * t];
        }

        // scores = Q @ K^T
        float s[16][4];
#pragma unroll
        for (int n = 0; n < 16; ++n)
#pragma unroll
            for (int i = 0; i < 4; ++i) s[n][i] = 0.0f;
#pragma unroll
        for (int jq = 0; jq < 8; ++jq) {
            uint32_t a0 = fau(qlo[jq].x), a1 = fau(qhi[jq].x);
            uint32_t a2 = fau(qlo[jq].y), a3 = fau(qhi[jq].y);
#pragma unroll
            for (int n = 0; n < 16; ++n) {
                float2 bb = *(const float2*)&Ks[(n * 8 + g) * 72 + jq * 8 + 2 * t];
                mma8(s[n], a0, a1, a2, a3, fau(bb.x), fau(bb.y));
            }
        }

        // softmax (rows r0+g / r0+g+8)
        float m0 = -1e30f, m1 = -1e30f;
#pragma unroll
        for (int n = 0; n < 16; ++n) {
            m0 = fmaxf(m0, fmaxf(s[n][0], s[n][1]));
            m1 = fmaxf(m1, fmaxf(s[n][2], s[n][3]));
        }
        m0 = fmaxf(m0, __shfl_xor_sync(0xffffffffu, m0, 1));
        m0 = fmaxf(m0, __shfl_xor_sync(0xffffffffu, m0, 2));
        m1 = fmaxf(m1, __shfl_xor_sync(0xffffffffu, m1, 1));
        m1 = fmaxf(m1, __shfl_xor_sync(0xffffffffu, m1, 2));

        float sum0 = 0.0f, sum1 = 0.0f;
#pragma unroll
        for (int n = 0; n < 16; ++n) {
            float p0 = exp2f((s[n][0] - m0) * L2E);
            float p1 = exp2f((s[n][1] - m0) * L2E);
            float p2 = exp2f((s[n][2] - m1) * L2E);
            float p3 = exp2f((s[n][3] - m1) * L2E);
            sum0 += p0 + p1;
            sum1 += p2 + p3;
            s[n][0] = f2tf(p0); s[n][1] = f2tf(p1);
            s[n][2] = f2tf(p2); s[n][3] = f2tf(p3);
        }
        sum0 += __shfl_xor_sync(0xffffffffu, sum0, 1);
        sum0 += __shfl_xor_sync(0xffffffffu, sum0, 2);
        sum1 += __shfl_xor_sync(0xffffffffu, sum1, 1);
        sum1 += __shfl_xor_sync(0xffffffffu, sum1, 2);
        float sc0 = 1.0f / sum0, sc1 = 1.0f / sum1;

        // O = P @ V
        float o[8][4];
#pragma unroll
        for (int j = 0; j < 8; ++j)
#pragma unroll
            for (int i = 0; i < 4; ++i) o[j][i] = 0.0f;
#pragma unroll
        for (int js = 0; js < 16; ++js) {
            uint32_t a0 = fau(s[js][0]);
            uint32_t a1 = fau(s[js][2]);
            uint32_t a2 = fau(s[js][1]);
            uint32_t a3 = fau(s[js][3]);
#pragma unroll
            for (int j = 0; j < 8; ++j) {
                float2 bb = *(const float2*)&Vt[(j * 8 + g) * 136 + js * 8 + 2 * t];
                mma8(o[j], a0, a1, a2, a3, fau(bb.x), fau(bb.y));
            }
        }

        // epilogue: out = relu(O/rowsum + R), R read back from Out
#pragma unroll
        for (int j = 0; j < 8; ++j) {
            float2 rlo = *(const float2*)&Out[ob + (size_t)(r0 + g) * HD_ + j * 8 + 2 * t];
            float2 rhi = *(const float2*)&Out[ob + (size_t)(r0 + g + 8) * HD_ + j * 8 + 2 * t];
            float2 lo, hi;
            lo.x = fmaxf(o[j][0] * sc0 + rlo.x, 0.0f);
            lo.y = fmaxf(o[j][1] * sc0 + rlo.y, 0.0f);
            hi.x = fmaxf(o[j][2] * sc1 + rhi.x, 0.0f);
            hi.y = fmaxf(o[j][3] * sc1 + rhi.y, 0.0f);
            *(float2*)&Out[ob + (size_t)(r0 + g) * HD_ + j * 8 + 2 * t] = lo;
            *(float2*)&Out[ob + (size_t)(r0 + g + 8) * HD_ + j * 8 + 2 * t] = hi;
        }
    }
}

extern "C" void kernel_launch(void* const* d_in, const int* in_sizes, int n_in,
                              void* d_out, int out_size) {
    const float* x  = (const float*)d_in[0];
    const float* wq = (const float*)d_in[1];
    const float* wk = (const float*)d_in[2];
    const float* wv = (const float*)d_in[3];
    const float* wr = (const float*)d_in[4];
    float* out = (float*)d_out;

    cudaFuncSetAttribute(mha_kernel, cudaFuncAttributeMaxDynamicSharedMemorySize, SMEM_BYTES);
    prep_kernel<<<2048, 256>>>(wq, wk, wv, wr);
    mha_kernel<<<1024, 256, SMEM_BYTES>>>(x, out);
}